// round 1
// baseline (speedup 1.0000x reference)
#include <cuda_runtime.h>
#include <cstdint>

// Shapes (fixed by the problem)
#define BB   32
#define SS   128
#define VV   8192
#define EE   256
#define MR   (BB*SS)      // 4096 rows for stage-1 GEMM

// ---------------- scratch (device globals; no allocation) ----------------
__device__ float g_h[MR*EE];            // h            [4096,256]   4 MB
__device__ float g_s[MR];               // rowsum(h)    [4096]
__device__ float g_weff[BB*EE*EE];      // Weff         [32,256,256] 8 MB
__device__ float g_y[MR*EE];            // y            [4096,256]   4 MB
__device__ float g_part[64*BB*EE];      // split-K partials for G4    2 MB
__device__ float g_y2[BB*EE];           // y2           [32,256]

// ---------------- helpers ----------------
__device__ __forceinline__ uint32_t f2tf32(float f) {
    uint32_t u;
    asm("cvt.rna.tf32.f32 %0, %1;" : "=r"(u) : "f"(f));
    return u;
}

__device__ __forceinline__ void mma_tf32(float c[4], const uint32_t a[4], const uint32_t b[2]) {
    asm volatile(
        "mma.sync.aligned.m16n8k8.row.col.f32.tf32.tf32.f32 "
        "{%0,%1,%2,%3}, {%4,%5,%6,%7}, {%8,%9}, {%0,%1,%2,%3};"
        : "+f"(c[0]), "+f"(c[1]), "+f"(c[2]), "+f"(c[3])
        : "r"(a[0]), "r"(a[1]), "r"(a[2]), "r"(a[3]), "r"(b[0]), "r"(b[1]));
}

// ---------------- generic tf32 GEMM: C = act(A @ B^T + bias) ----------------
// A[M,K] row-major, B[N,K] row-major. Tiles: BM=64, BN=64, BK=32.
// 128 threads = 4 warps, warp tile 32x32 (2x2 warp grid).
// Reg-prefetch + ping-pong smem double buffering. All dims divide tiles exactly.
#define SMSTRIDE 36   // 32 + 4 pad: conflict-free fragment LDS and aligned uint4 STS

template <bool RELU>
__device__ __forceinline__ void gemm_body(
    const float* __restrict__ A, long lda, long strideA,
    const float* __restrict__ B, long ldb, long strideB,
    float* __restrict__ C, long ldc, long strideC,
    const float* __restrict__ bias, int K)
{
    __shared__ uint32_t sA[2][64 * SMSTRIDE];
    __shared__ uint32_t sB[2][64 * SMSTRIDE];

    const int tid  = threadIdx.x;
    const int lane = tid & 31;
    const int warp = tid >> 5;
    const int wm = (warp >> 1) * 32;      // warp row offset in tile
    const int wn = (warp & 1) * 32;       // warp col offset in tile
    const long bm = (long)blockIdx.y * 64;
    const long bn = (long)blockIdx.x * 64;

    A += (long)blockIdx.z * strideA;
    B += (long)blockIdx.z * strideB;
    C += (long)blockIdx.z * strideC;

    const int srow = tid >> 3;            // 0..15 (staging row base)
    const int scol = (tid & 7) * 4;       // 0..28 (staging col, float4)

    float acc[2][4][4] = {};
    float4 pa[4], pb[4];

    // prefetch tile 0
    #pragma unroll
    for (int i = 0; i < 4; i++) {
        int r = srow + 16 * i;
        pa[i] = *reinterpret_cast<const float4*>(&A[(bm + r) * lda + 0 + scol]);
        pb[i] = *reinterpret_cast<const float4*>(&B[(bn + r) * ldb + 0 + scol]);
    }
    #pragma unroll
    for (int i = 0; i < 4; i++) {
        int r = srow + 16 * i;
        uint4 au = { f2tf32(pa[i].x), f2tf32(pa[i].y), f2tf32(pa[i].z), f2tf32(pa[i].w) };
        uint4 bu = { f2tf32(pb[i].x), f2tf32(pb[i].y), f2tf32(pb[i].z), f2tf32(pb[i].w) };
        *reinterpret_cast<uint4*>(&sA[0][r * SMSTRIDE + scol]) = au;
        *reinterpret_cast<uint4*>(&sB[0][r * SMSTRIDE + scol]) = bu;
    }
    __syncthreads();

    const int nk = K >> 5;
    for (int kt = 0; kt < nk; kt++) {
        const int cur = kt & 1;
        const bool more = (kt + 1) < nk;

        // prefetch next tile (global -> regs), hidden under compute
        if (more) {
            int k0 = (kt + 1) << 5;
            #pragma unroll
            for (int i = 0; i < 4; i++) {
                int r = srow + 16 * i;
                pa[i] = *reinterpret_cast<const float4*>(&A[(bm + r) * lda + k0 + scol]);
                pb[i] = *reinterpret_cast<const float4*>(&B[(bn + r) * ldb + k0 + scol]);
            }
        }

        const uint32_t* As = sA[cur];
        const uint32_t* Bs = sB[cur];
        #pragma unroll
        for (int ks = 0; ks < 4; ks++) {
            uint32_t a[2][4], b[4][2];
            const int ar = lane >> 2;
            const int ac = ks * 8 + (lane & 3);
            #pragma unroll
            for (int mt = 0; mt < 2; mt++) {
                int r = wm + mt * 16 + ar;
                a[mt][0] = As[r * SMSTRIDE + ac];
                a[mt][1] = As[(r + 8) * SMSTRIDE + ac];
                a[mt][2] = As[r * SMSTRIDE + ac + 4];
                a[mt][3] = As[(r + 8) * SMSTRIDE + ac + 4];
            }
            #pragma unroll
            for (int nt = 0; nt < 4; nt++) {
                int n = wn + nt * 8 + ar;
                b[nt][0] = Bs[n * SMSTRIDE + ac];
                b[nt][1] = Bs[n * SMSTRIDE + ac + 4];
            }
            #pragma unroll
            for (int mt = 0; mt < 2; mt++)
                #pragma unroll
                for (int nt = 0; nt < 4; nt++)
                    mma_tf32(acc[mt][nt], a[mt], b[nt]);
        }

        if (more) {
            #pragma unroll
            for (int i = 0; i < 4; i++) {
                int r = srow + 16 * i;
                uint4 au = { f2tf32(pa[i].x), f2tf32(pa[i].y), f2tf32(pa[i].z), f2tf32(pa[i].w) };
                uint4 bu = { f2tf32(pb[i].x), f2tf32(pb[i].y), f2tf32(pb[i].z), f2tf32(pb[i].w) };
                *reinterpret_cast<uint4*>(&sA[cur ^ 1][r * SMSTRIDE + scol]) = au;
                *reinterpret_cast<uint4*>(&sB[cur ^ 1][r * SMSTRIDE + scol]) = bu;
            }
        }
        __syncthreads();
    }

    // epilogue: bias (+relu), float2 stores
    #pragma unroll
    for (int mt = 0; mt < 2; mt++) {
        #pragma unroll
        for (int nt = 0; nt < 4; nt++) {
            long row = bm + wm + mt * 16 + (lane >> 2);
            long col = bn + wn + nt * 8 + (lane & 3) * 2;
            float b0 = bias[col], b1 = bias[col + 1];
            float v0 = acc[mt][nt][0] + b0;
            float v1 = acc[mt][nt][1] + b1;
            float v2 = acc[mt][nt][2] + b0;
            float v3 = acc[mt][nt][3] + b1;
            if (RELU) {
                v0 = fmaxf(v0, 0.f); v1 = fmaxf(v1, 0.f);
                v2 = fmaxf(v2, 0.f); v3 = fmaxf(v3, 0.f);
            }
            *reinterpret_cast<float2*>(&C[row * ldc + col])       = make_float2(v0, v1);
            *reinterpret_cast<float2*>(&C[(row + 8) * ldc + col]) = make_float2(v2, v3);
        }
    }
}

// G1: h = relu(x @ w_emb^T + b_emb)   grid(4,64,1) x 128
__global__ void __launch_bounds__(128) gemm1_kernel(
    const float* __restrict__ x, const float* __restrict__ w_emb,
    const float* __restrict__ b_emb)
{
    gemm_body<true>(x, VV, 0, w_emb, VV, 0, g_h, EE, 0, b_emb, VV);
}

// G3: y[b] = relu(h[b] @ Weff[b]^T + b_red)   grid(4,2,32) x 128
__global__ void __launch_bounds__(128) gemm3_kernel(const float* __restrict__ b_red)
{
    gemm_body<true>(g_h, EE, (long)SS * EE, g_weff, EE, (long)EE * EE,
                    g_y, EE, (long)SS * EE, b_red, EE);
}

// ---------------- rowsum: s[r] = sum_j h[r,j] ----------------  grid(512) x 256
__global__ void rowsum_kernel()
{
    int r = blockIdx.x * 8 + (threadIdx.x >> 5);
    int lane = threadIdx.x & 31;
    float s = 0.f;
    #pragma unroll
    for (int i = 0; i < 8; i++) s += g_h[(long)r * EE + lane + i * 32];
    #pragma unroll
    for (int o = 16; o; o >>= 1) s += __shfl_xor_sync(0xffffffffu, s, o);
    if (lane == 0) g_s[r] = s;
}

// ---------------- G2: Weff[b,e,j] = sum_k s[b,k]*w_red[e, k*E+j] ----------------
// grid(256=e) x 256(=j)
__global__ void __launch_bounds__(256) weff_kernel(const float* __restrict__ w_red)
{
    __shared__ float ss[BB * SS];
    int tid = threadIdx.x;
    for (int i = tid; i < BB * SS; i += 256) ss[i] = g_s[i];
    __syncthreads();

    int e = blockIdx.x;
    const float* w = w_red + (long)e * (SS * EE) + tid;   // j = tid
    float acc[BB];
    #pragma unroll
    for (int b = 0; b < BB; b++) acc[b] = 0.f;

    #pragma unroll 8
    for (int k = 0; k < SS; k++) {
        float wv = w[(long)k * EE];
        #pragma unroll
        for (int b = 0; b < BB; b++) acc[b] += ss[b * SS + k] * wv;
    }
    #pragma unroll
    for (int b = 0; b < BB; b++)
        g_weff[(long)b * (EE * EE) + (long)e * EE + tid] = acc[b];
}

// ---------------- G4 split-K: partial[ks,b,e] over K-chunk of 512 ----------------
// grid(4 = e-block, 64 = k-split) x 256
__global__ void __launch_bounds__(256) red2_partial_kernel(const float* __restrict__ w_red2)
{
    __shared__ float ys[32][68];
    __shared__ float ws[64][65];
    int tid = threadIdx.x;
    int e_base = blockIdx.x * 64;
    long k_base = (long)blockIdx.y * 512;
    int el = tid & 63;
    int bb = (tid >> 6) * 8;
    float acc[8] = {};

    for (int k0 = 0; k0 < 512; k0 += 64) {
        #pragma unroll
        for (int i = 0; i < 2; i++) {
            int idx = tid + i * 256;          // 0..511 float4 slots
            int row = idx >> 4;               // 32 rows of y
            int c4 = (idx & 15) * 4;
            float4 v = *reinterpret_cast<const float4*>(
                &g_y[(long)row * (SS * EE) + k_base + k0 + c4]);
            *reinterpret_cast<float4*>(&ys[row][c4]) = v;
        }
        #pragma unroll
        for (int i = 0; i < 4; i++) {
            int idx = tid + i * 256;          // 0..1023 float4 slots
            int row = idx >> 4;               // 64 rows of w_red2
            int c4 = (idx & 15) * 4;
            float4 v = *reinterpret_cast<const float4*>(
                &w_red2[(long)(e_base + row) * (SS * EE) + k_base + k0 + c4]);
            ws[row][c4] = v.x; ws[row][c4 + 1] = v.y;
            ws[row][c4 + 2] = v.z; ws[row][c4 + 3] = v.w;
        }
        __syncthreads();
        #pragma unroll 8
        for (int kk = 0; kk < 64; kk++) {
            float wv = ws[el][kk];
            #pragma unroll
            for (int i = 0; i < 8; i++) acc[i] += ys[bb + i][kk] * wv;
        }
        __syncthreads();
    }
    #pragma unroll
    for (int i = 0; i < 8; i++)
        g_part[(long)blockIdx.y * (BB * EE) + (bb + i) * EE + e_base + el] = acc[i];
}

// reduce partials -> y2 = relu(. + b_red2)   grid(32) x 256
__global__ void red2_reduce_kernel(const float* __restrict__ b_red2)
{
    int idx = blockIdx.x * 256 + threadIdx.x;       // b*256+e
    float s = b_red2[idx & 255];
    #pragma unroll 8
    for (int ks = 0; ks < 64; ks++) s += g_part[(long)ks * (BB * EE) + idx];
    g_y2[idx] = fmaxf(s, 0.f);
}

// ---------------- G5: out = y2 @ w_out^T + b_out ----------------
// grid(128 = v-block of 64) x 256
__global__ void __launch_bounds__(256) out_kernel(
    const float* __restrict__ w_out, const float* __restrict__ b_out,
    float* __restrict__ out)
{
    __shared__ float ys[32][68];
    __shared__ float ws[64][65];
    int tid = threadIdx.x;
    int v_base = blockIdx.x * 64;
    int vl = tid & 63;
    int bb = (tid >> 6) * 8;
    float acc[8] = {};

    for (int k0 = 0; k0 < EE; k0 += 64) {
        #pragma unroll
        for (int i = 0; i < 2; i++) {
            int idx = tid + i * 256;
            int row = idx >> 4;
            int c4 = (idx & 15) * 4;
            float4 v = *reinterpret_cast<const float4*>(&g_y2[row * EE + k0 + c4]);
            *reinterpret_cast<float4*>(&ys[row][c4]) = v;
        }
        #pragma unroll
        for (int i = 0; i < 4; i++) {
            int idx = tid + i * 256;
            int row = idx >> 4;
            int c4 = (idx & 15) * 4;
            float4 v = *reinterpret_cast<const float4*>(
                &w_out[(long)(v_base + row) * EE + k0 + c4]);
            ws[row][c4] = v.x; ws[row][c4 + 1] = v.y;
            ws[row][c4 + 2] = v.z; ws[row][c4 + 3] = v.w;
        }
        __syncthreads();
        #pragma unroll 8
        for (int kk = 0; kk < 64; kk++) {
            float wv = ws[vl][kk];
            #pragma unroll
            for (int i = 0; i < 8; i++) acc[i] += ys[bb + i][kk] * wv;
        }
        __syncthreads();
    }
    float bo = b_out[v_base + vl];
    #pragma unroll
    for (int i = 0; i < 8; i++)
        out[(long)(bb + i) * VV + v_base + vl] = acc[i] + bo;
}

// ---------------- launch ----------------
extern "C" void kernel_launch(void* const* d_in, const int* in_sizes, int n_in,
                              void* d_out, int out_size)
{
    const float* x      = (const float*)d_in[0];
    const float* w_emb  = (const float*)d_in[1];
    const float* b_emb  = (const float*)d_in[2];
    const float* w_red  = (const float*)d_in[3];
    const float* b_red  = (const float*)d_in[4];
    const float* w_red2 = (const float*)d_in[5];
    const float* b_red2 = (const float*)d_in[6];
    const float* w_out  = (const float*)d_in[7];
    const float* b_out  = (const float*)d_in[8];
    float* out = (float*)d_out;

    gemm1_kernel<<<dim3(4, 64, 1), 128>>>(x, w_emb, b_emb);          // h
    rowsum_kernel<<<512, 256>>>();                                    // s
    weff_kernel<<<256, 256>>>(w_red);                                 // Weff
    gemm3_kernel<<<dim3(4, 2, 32), 128>>>(b_red);                     // y
    red2_partial_kernel<<<dim3(4, 64), 256>>>(w_red2);                // G4 partials
    red2_reduce_kernel<<<32, 256>>>(b_red2);                          // y2
    out_kernel<<<128, 256>>>(w_out, b_out, out);                      // out
}

// round 2
// speedup vs baseline: 1.2599x; 1.2599x over previous
#include <cuda_runtime.h>
#include <cstdint>

// Shapes (fixed by the problem)
#define BB   32
#define SS   128
#define VV   8192
#define EE   256
#define MR   (BB*SS)      // 4096 rows for stage-1 GEMM

// G1 split-K config
#define KSPLIT 8
#define KCHUNK (VV/KSPLIT)   // 1024
#define G1_STR 20            // 16 + 4 pad (uint32 units)

// ---------------- scratch (device globals; no allocation) ----------------
__device__ float g_p1[KSPLIT][MR][EE];  // G1 split-K partials  32 MB
__device__ float g_h[MR*EE];            // h            [4096,256]   4 MB
__device__ float g_s[MR];               // rowsum(h)    [4096]
__device__ float g_weff[BB*EE*EE];      // Weff         [32,256,256] 8 MB
__device__ float g_y[MR*EE];            // y            [4096,256]   4 MB
__device__ float g_part[64*BB*EE];      // split-K partials for G4    2 MB
__device__ float g_y2[BB*EE];           // y2           [32,256]

// ---------------- helpers ----------------
__device__ __forceinline__ uint32_t f2tf32(float f) {
    uint32_t u;
    asm("cvt.rna.tf32.f32 %0, %1;" : "=r"(u) : "f"(f));
    return u;
}

__device__ __forceinline__ void mma_tf32(float c[4], const uint32_t a[4], const uint32_t b[2]) {
    asm volatile(
        "mma.sync.aligned.m16n8k8.row.col.f32.tf32.tf32.f32 "
        "{%0,%1,%2,%3}, {%4,%5,%6,%7}, {%8,%9}, {%0,%1,%2,%3};"
        : "+f"(c[0]), "+f"(c[1]), "+f"(c[2]), "+f"(c[3])
        : "r"(a[0]), "r"(a[1]), "r"(a[2]), "r"(a[3]), "r"(b[0]), "r"(b[1]));
}

// ===================================================================
// G1 split-K: partial[kz] = x[:, kz*1024:(kz+1)*1024] @ w_emb^T chunk
// Block tile 128x128, BK=16, 256 threads = 8 warps (4m x 2n),
// warp tile 32x64. Double-buffered smem + reg prefetch.
// grid (2 = n/128, 32 = m/128, 8 = ksplit)
// ===================================================================
__global__ void __launch_bounds__(256, 2) gemm1_split_kernel(
    const float* __restrict__ x, const float* __restrict__ w_emb)
{
    __shared__ uint32_t sA[2][128 * G1_STR];
    __shared__ uint32_t sB[2][128 * G1_STR];

    const int tid  = threadIdx.x;
    const int lane = tid & 31;
    const int warp = tid >> 5;
    const int wm = (warp >> 1) * 32;      // warp m offset (0,32,64,96)
    const int wn = (warp & 1) * 64;       // warp n offset (0,64)
    const long bm = (long)blockIdx.y * 128;
    const long bn = (long)blockIdx.x * 128;
    const long kbase = (long)blockIdx.z * KCHUNK;

    const int srow = tid >> 2;            // 0..63 (staging row base)
    const int scol = (tid & 3) * 4;       // 0,4,8,12 (staging col, float4)

    float acc[2][8][4] = {};
    float4 pa[2], pb[2];

    // prefetch tile 0
    #pragma unroll
    for (int i = 0; i < 2; i++) {
        int r = srow + 64 * i;
        pa[i] = *reinterpret_cast<const float4*>(&x[(bm + r) * VV + kbase + scol]);
        pb[i] = *reinterpret_cast<const float4*>(&w_emb[(bn + r) * VV + kbase + scol]);
    }
    #pragma unroll
    for (int i = 0; i < 2; i++) {
        int r = srow + 64 * i;
        uint4 au = { f2tf32(pa[i].x), f2tf32(pa[i].y), f2tf32(pa[i].z), f2tf32(pa[i].w) };
        uint4 bu = { f2tf32(pb[i].x), f2tf32(pb[i].y), f2tf32(pb[i].z), f2tf32(pb[i].w) };
        *reinterpret_cast<uint4*>(&sA[0][r * G1_STR + scol]) = au;
        *reinterpret_cast<uint4*>(&sB[0][r * G1_STR + scol]) = bu;
    }
    __syncthreads();

    const int nkt = KCHUNK / 16;          // 64 k-tiles
    for (int kt = 0; kt < nkt; kt++) {
        const int cur = kt & 1;
        const bool more = (kt + 1) < nkt;

        if (more) {
            long k0 = kbase + (long)(kt + 1) * 16;
            #pragma unroll
            for (int i = 0; i < 2; i++) {
                int r = srow + 64 * i;
                pa[i] = *reinterpret_cast<const float4*>(&x[(bm + r) * VV + k0 + scol]);
                pb[i] = *reinterpret_cast<const float4*>(&w_emb[(bn + r) * VV + k0 + scol]);
            }
        }

        const uint32_t* As = sA[cur];
        const uint32_t* Bs = sB[cur];
        const int ar = lane >> 2;
        #pragma unroll
        for (int ks = 0; ks < 2; ks++) {
            const int ac = ks * 8 + (lane & 3);
            uint32_t a[2][4], b[8][2];
            #pragma unroll
            for (int mt = 0; mt < 2; mt++) {
                int r = wm + mt * 16 + ar;
                a[mt][0] = As[r * G1_STR + ac];
                a[mt][1] = As[(r + 8) * G1_STR + ac];
                a[mt][2] = As[r * G1_STR + ac + 4];
                a[mt][3] = As[(r + 8) * G1_STR + ac + 4];
            }
            #pragma unroll
            for (int nt = 0; nt < 8; nt++) {
                int n = wn + nt * 8 + ar;
                b[nt][0] = Bs[n * G1_STR + ac];
                b[nt][1] = Bs[n * G1_STR + ac + 4];
            }
            #pragma unroll
            for (int mt = 0; mt < 2; mt++)
                #pragma unroll
                for (int nt = 0; nt < 8; nt++)
                    mma_tf32(acc[mt][nt], a[mt], b[nt]);
        }

        if (more) {
            #pragma unroll
            for (int i = 0; i < 2; i++) {
                int r = srow + 64 * i;
                uint4 au = { f2tf32(pa[i].x), f2tf32(pa[i].y), f2tf32(pa[i].z), f2tf32(pa[i].w) };
                uint4 bu = { f2tf32(pb[i].x), f2tf32(pb[i].y), f2tf32(pb[i].z), f2tf32(pb[i].w) };
                *reinterpret_cast<uint4*>(&sA[cur ^ 1][r * G1_STR + scol]) = au;
                *reinterpret_cast<uint4*>(&sB[cur ^ 1][r * G1_STR + scol]) = bu;
            }
        }
        __syncthreads();
    }

    // epilogue: raw partials (no bias/relu here)
    float* P = &g_p1[blockIdx.z][0][0];
    #pragma unroll
    for (int mt = 0; mt < 2; mt++) {
        #pragma unroll
        for (int nt = 0; nt < 8; nt++) {
            long row = bm + wm + mt * 16 + (lane >> 2);
            long col = bn + wn + nt * 8 + (lane & 3) * 2;
            *reinterpret_cast<float2*>(&P[row * EE + col]) =
                make_float2(acc[mt][nt][0], acc[mt][nt][1]);
            *reinterpret_cast<float2*>(&P[(row + 8) * EE + col]) =
                make_float2(acc[mt][nt][2], acc[mt][nt][3]);
        }
    }
}

// reduce split-K partials -> h = relu(sum + bias); also rowsum -> s.
// grid(4096) x 256. Fixed-order sum => deterministic.
__global__ void __launch_bounds__(256) h_reduce_kernel(const float* __restrict__ b_emb)
{
    const int row = blockIdx.x;
    const int e = threadIdx.x;
    const int lane = e & 31;
    const int warp = e >> 5;

    float v = b_emb[e];
    #pragma unroll
    for (int ks = 0; ks < KSPLIT; ks++) v += g_p1[ks][row][e];
    v = fmaxf(v, 0.f);
    g_h[(long)row * EE + e] = v;

    float s = v;
    #pragma unroll
    for (int o = 16; o; o >>= 1) s += __shfl_xor_sync(0xffffffffu, s, o);
    __shared__ float red[8];
    if (lane == 0) red[warp] = s;
    __syncthreads();
    if (e == 0) {
        float t = 0.f;
        #pragma unroll
        for (int i = 0; i < 8; i++) t += red[i];
        g_s[row] = t;
    }
}

// ---------------- generic tf32 GEMM (64x64 tile, used for G3) ----------------
#define SMSTRIDE 36

template <bool RELU>
__device__ __forceinline__ void gemm_body(
    const float* __restrict__ A, long lda, long strideA,
    const float* __restrict__ B, long ldb, long strideB,
    float* __restrict__ C, long ldc, long strideC,
    const float* __restrict__ bias, int K)
{
    __shared__ uint32_t sA[2][64 * SMSTRIDE];
    __shared__ uint32_t sB[2][64 * SMSTRIDE];

    const int tid  = threadIdx.x;
    const int lane = tid & 31;
    const int warp = tid >> 5;
    const int wm = (warp >> 1) * 32;
    const int wn = (warp & 1) * 32;
    const long bm = (long)blockIdx.y * 64;
    const long bn = (long)blockIdx.x * 64;

    A += (long)blockIdx.z * strideA;
    B += (long)blockIdx.z * strideB;
    C += (long)blockIdx.z * strideC;

    const int srow = tid >> 3;
    const int scol = (tid & 7) * 4;

    float acc[2][4][4] = {};
    float4 pa[4], pb[4];

    #pragma unroll
    for (int i = 0; i < 4; i++) {
        int r = srow + 16 * i;
        pa[i] = *reinterpret_cast<const float4*>(&A[(bm + r) * lda + 0 + scol]);
        pb[i] = *reinterpret_cast<const float4*>(&B[(bn + r) * ldb + 0 + scol]);
    }
    #pragma unroll
    for (int i = 0; i < 4; i++) {
        int r = srow + 16 * i;
        uint4 au = { f2tf32(pa[i].x), f2tf32(pa[i].y), f2tf32(pa[i].z), f2tf32(pa[i].w) };
        uint4 bu = { f2tf32(pb[i].x), f2tf32(pb[i].y), f2tf32(pb[i].z), f2tf32(pb[i].w) };
        *reinterpret_cast<uint4*>(&sA[0][r * SMSTRIDE + scol]) = au;
        *reinterpret_cast<uint4*>(&sB[0][r * SMSTRIDE + scol]) = bu;
    }
    __syncthreads();

    const int nk = K >> 5;
    for (int kt = 0; kt < nk; kt++) {
        const int cur = kt & 1;
        const bool more = (kt + 1) < nk;

        if (more) {
            int k0 = (kt + 1) << 5;
            #pragma unroll
            for (int i = 0; i < 4; i++) {
                int r = srow + 16 * i;
                pa[i] = *reinterpret_cast<const float4*>(&A[(bm + r) * lda + k0 + scol]);
                pb[i] = *reinterpret_cast<const float4*>(&B[(bn + r) * ldb + k0 + scol]);
            }
        }

        const uint32_t* As = sA[cur];
        const uint32_t* Bs = sB[cur];
        #pragma unroll
        for (int ks = 0; ks < 4; ks++) {
            uint32_t a[2][4], b[4][2];
            const int ar = lane >> 2;
            const int ac = ks * 8 + (lane & 3);
            #pragma unroll
            for (int mt = 0; mt < 2; mt++) {
                int r = wm + mt * 16 + ar;
                a[mt][0] = As[r * SMSTRIDE + ac];
                a[mt][1] = As[(r + 8) * SMSTRIDE + ac];
                a[mt][2] = As[r * SMSTRIDE + ac + 4];
                a[mt][3] = As[(r + 8) * SMSTRIDE + ac + 4];
            }
            #pragma unroll
            for (int nt = 0; nt < 4; nt++) {
                int n = wn + nt * 8 + ar;
                b[nt][0] = Bs[n * SMSTRIDE + ac];
                b[nt][1] = Bs[n * SMSTRIDE + ac + 4];
            }
            #pragma unroll
            for (int mt = 0; mt < 2; mt++)
                #pragma unroll
                for (int nt = 0; nt < 4; nt++)
                    mma_tf32(acc[mt][nt], a[mt], b[nt]);
        }

        if (more) {
            #pragma unroll
            for (int i = 0; i < 4; i++) {
                int r = srow + 16 * i;
                uint4 au = { f2tf32(pa[i].x), f2tf32(pa[i].y), f2tf32(pa[i].z), f2tf32(pa[i].w) };
                uint4 bu = { f2tf32(pb[i].x), f2tf32(pb[i].y), f2tf32(pb[i].z), f2tf32(pb[i].w) };
                *reinterpret_cast<uint4*>(&sA[cur ^ 1][r * SMSTRIDE + scol]) = au;
                *reinterpret_cast<uint4*>(&sB[cur ^ 1][r * SMSTRIDE + scol]) = bu;
            }
        }
        __syncthreads();
    }

    #pragma unroll
    for (int mt = 0; mt < 2; mt++) {
        #pragma unroll
        for (int nt = 0; nt < 4; nt++) {
            long row = bm + wm + mt * 16 + (lane >> 2);
            long col = bn + wn + nt * 8 + (lane & 3) * 2;
            float b0 = bias[col], b1 = bias[col + 1];
            float v0 = acc[mt][nt][0] + b0;
            float v1 = acc[mt][nt][1] + b1;
            float v2 = acc[mt][nt][2] + b0;
            float v3 = acc[mt][nt][3] + b1;
            if (RELU) {
                v0 = fmaxf(v0, 0.f); v1 = fmaxf(v1, 0.f);
                v2 = fmaxf(v2, 0.f); v3 = fmaxf(v3, 0.f);
            }
            *reinterpret_cast<float2*>(&C[row * ldc + col])       = make_float2(v0, v1);
            *reinterpret_cast<float2*>(&C[(row + 8) * ldc + col]) = make_float2(v2, v3);
        }
    }
}

// G3: y[b] = relu(h[b] @ Weff[b]^T + b_red)   grid(4,2,32) x 128
__global__ void __launch_bounds__(128) gemm3_kernel(const float* __restrict__ b_red)
{
    gemm_body<true>(g_h, EE, (long)SS * EE, g_weff, EE, (long)EE * EE,
                    g_y, EE, (long)SS * EE, b_red, EE);
}

// ---------------- G2: Weff[b,e,j] = sum_k s[b,k]*w_red[e, k*E+j] ----------------
__global__ void __launch_bounds__(256) weff_kernel(const float* __restrict__ w_red)
{
    __shared__ float ss[BB * SS];
    int tid = threadIdx.x;
    for (int i = tid; i < BB * SS; i += 256) ss[i] = g_s[i];
    __syncthreads();

    int e = blockIdx.x;
    const float* w = w_red + (long)e * (SS * EE) + tid;   // j = tid
    float acc[BB];
    #pragma unroll
    for (int b = 0; b < BB; b++) acc[b] = 0.f;

    #pragma unroll 8
    for (int k = 0; k < SS; k++) {
        float wv = w[(long)k * EE];
        #pragma unroll
        for (int b = 0; b < BB; b++) acc[b] += ss[b * SS + k] * wv;
    }
    #pragma unroll
    for (int b = 0; b < BB; b++)
        g_weff[(long)b * (EE * EE) + (long)e * EE + tid] = acc[b];
}

// ---------------- G4 split-K: partial[ks,b,e] over K-chunk of 512 ----------------
__global__ void __launch_bounds__(256) red2_partial_kernel(const float* __restrict__ w_red2)
{
    __shared__ float ys[32][68];
    __shared__ float ws[64][65];
    int tid = threadIdx.x;
    int e_base = blockIdx.x * 64;
    long k_base = (long)blockIdx.y * 512;
    int el = tid & 63;
    int bb = (tid >> 6) * 8;
    float acc[8] = {};

    for (int k0 = 0; k0 < 512; k0 += 64) {
        #pragma unroll
        for (int i = 0; i < 2; i++) {
            int idx = tid + i * 256;
            int row = idx >> 4;
            int c4 = (idx & 15) * 4;
            float4 v = *reinterpret_cast<const float4*>(
                &g_y[(long)row * (SS * EE) + k_base + k0 + c4]);
            *reinterpret_cast<float4*>(&ys[row][c4]) = v;
        }
        #pragma unroll
        for (int i = 0; i < 4; i++) {
            int idx = tid + i * 256;
            int row = idx >> 4;
            int c4 = (idx & 15) * 4;
            float4 v = *reinterpret_cast<const float4*>(
                &w_red2[(long)(e_base + row) * (SS * EE) + k_base + k0 + c4]);
            ws[row][c4] = v.x; ws[row][c4 + 1] = v.y;
            ws[row][c4 + 2] = v.z; ws[row][c4 + 3] = v.w;
        }
        __syncthreads();
        #pragma unroll 8
        for (int kk = 0; kk < 64; kk++) {
            float wv = ws[el][kk];
            #pragma unroll
            for (int i = 0; i < 8; i++) acc[i] += ys[bb + i][kk] * wv;
        }
        __syncthreads();
    }
    #pragma unroll
    for (int i = 0; i < 8; i++)
        g_part[(long)blockIdx.y * (BB * EE) + (bb + i) * EE + e_base + el] = acc[i];
}

// reduce partials -> y2 = relu(. + b_red2)   grid(32) x 256
__global__ void red2_reduce_kernel(const float* __restrict__ b_red2)
{
    int idx = blockIdx.x * 256 + threadIdx.x;
    float s = b_red2[idx & 255];
    #pragma unroll 8
    for (int ks = 0; ks < 64; ks++) s += g_part[(long)ks * (BB * EE) + idx];
    g_y2[idx] = fmaxf(s, 0.f);
}

// ---------------- G5: out = y2 @ w_out^T + b_out ----------------
__global__ void __launch_bounds__(256) out_kernel(
    const float* __restrict__ w_out, const float* __restrict__ b_out,
    float* __restrict__ out)
{
    __shared__ float ys[32][68];
    __shared__ float ws[64][65];
    int tid = threadIdx.x;
    int v_base = blockIdx.x * 64;
    int vl = tid & 63;
    int bb = (tid >> 6) * 8;
    float acc[8] = {};

    for (int k0 = 0; k0 < EE; k0 += 64) {
        #pragma unroll
        for (int i = 0; i < 2; i++) {
            int idx = tid + i * 256;
            int row = idx >> 4;
            int c4 = (idx & 15) * 4;
            float4 v = *reinterpret_cast<const float4*>(&g_y2[row * EE + k0 + c4]);
            *reinterpret_cast<float4*>(&ys[row][c4]) = v;
        }
        #pragma unroll
        for (int i = 0; i < 4; i++) {
            int idx = tid + i * 256;
            int row = idx >> 4;
            int c4 = (idx & 15) * 4;
            float4 v = *reinterpret_cast<const float4*>(
                &w_out[(long)(v_base + row) * EE + k0 + c4]);
            ws[row][c4] = v.x; ws[row][c4 + 1] = v.y;
            ws[row][c4 + 2] = v.z; ws[row][c4 + 3] = v.w;
        }
        __syncthreads();
        #pragma unroll 8
        for (int kk = 0; kk < 64; kk++) {
            float wv = ws[vl][kk];
            #pragma unroll
            for (int i = 0; i < 8; i++) acc[i] += ys[bb + i][kk] * wv;
        }
        __syncthreads();
    }
    float bo = b_out[v_base + vl];
    #pragma unroll
    for (int i = 0; i < 8; i++)
        out[(long)(bb + i) * VV + v_base + vl] = acc[i] + bo;
}

// ---------------- launch ----------------
extern "C" void kernel_launch(void* const* d_in, const int* in_sizes, int n_in,
                              void* d_out, int out_size)
{
    const float* x      = (const float*)d_in[0];
    const float* w_emb  = (const float*)d_in[1];
    const float* b_emb  = (const float*)d_in[2];
    const float* w_red  = (const float*)d_in[3];
    const float* b_red  = (const float*)d_in[4];
    const float* w_red2 = (const float*)d_in[5];
    const float* b_red2 = (const float*)d_in[6];
    const float* w_out  = (const float*)d_in[7];
    const float* b_out  = (const float*)d_in[8];
    float* out = (float*)d_out;

    gemm1_split_kernel<<<dim3(2, 32, KSPLIT), 256>>>(x, w_emb);       // G1 partials
    h_reduce_kernel<<<MR, 256>>>(b_emb);                              // h + rowsum
    weff_kernel<<<256, 256>>>(w_red);                                 // Weff
    gemm3_kernel<<<dim3(4, 2, 32), 128>>>(b_red);                     // y
    red2_partial_kernel<<<dim3(4, 64), 256>>>(w_red2);                // G4 partials
    red2_reduce_kernel<<<32, 256>>>(b_red2);                          // y2
    out_kernel<<<128, 256>>>(w_out, b_out, out);                      // out
}